// round 11
// baseline (speedup 1.0000x reference)
#include <cuda_runtime.h>
#include <cuda_bf16.h>
#include <math.h>
#include <stdint.h>

#define NIMG   16
#define NANCH  8732
#define NCLS   80
#define FLATC  (NANCH * NCLS)     // 698560
#define NCAND  400
#define NOUT   200
#define CAP    4096
#define CLIPV  4.135166556742356f // log(1000/16)

// ---------------- device scratch (no allocations allowed) ----------------
__device__ float        g_cls[(size_t)NIMG * NANCH * 81];   // logits
__device__ float        g_scr[(size_t)NIMG * FLATC];        // thresholded softmax scores
__device__ float        g_reg[(size_t)NIMG * NANCH * 4];    // box deltas
__device__ unsigned int g_hist[NIMG * 65536];
__device__ int          g_cnt[NIMG];
__device__ unsigned int g_thr[NIMG];
__device__ float        g_cand_v[NIMG * CAP];
__device__ int          g_cand_i[NIMG * CAP];
__device__ float        g_top_v[NIMG * NCAND];
__device__ int          g_top_i[NIMG * NCAND];

// ---------------- zero histograms ----------------
__global__ void zero_kernel()
{
    int i  = blockIdx.x * blockDim.x + threadIdx.x;
    int st = gridDim.x * blockDim.x;
    for (int t = i; t < NIMG * 65536; t += st) g_hist[t] = 0u;
}

// ---------------- merged fused cls+reg conv heads: ONE launch -------------
// 804-CTA grid (biggest-K first), 256 threads, 128x128x16 tile, 8Mx8N
// microtile in packed FFMA2. NEW: 4-stage smem ring (dynamic 96KB) with the
// STS for chunk ch+1 issued a full compute-phase before the barrier that
// publishes it -> kills the BAR-side STS drain + post-bar LDS ramp.
// Per-output k-order and 192-k cascade grouping unchanged -> bitwise
// identical results to the passing round-8/10 kernels.
struct HeadPtrs {
    const float* feat[6];
    const float* cw[6];
    const float* cb[6];
    const float* rw[6];
    const float* rb[6];
};

__device__ __constant__ int d_C[6]    = {512, 1024, 512, 256, 256, 256};
__device__ __constant__ int d_H[6]    = {38, 19, 10, 5, 3, 1};
__device__ __constant__ int d_AN[6]   = {4, 6, 6, 6, 4, 4};
__device__ __constant__ int d_AOFF[6] = {0, 5776, 7942, 8542, 8692, 8728};
__device__ __constant__ int d_NX[6]   = {181, 46, 13, 4, 2, 1};  // ceil(Nc/128)

#define GEMM_SMEM (4 * 16 * 128 * 12)   // 98304 B: 4-stage (A dup f32x2 + B f32)

__global__ void __launch_bounds__(256, 1)
head_gemm_all(const HeadPtrs P)
{
    // ---- block -> (level, tile) mapping; work-heavy levels first ----
    const int b = blockIdx.x;
    int li, rel;
    if      (b < 184) { li = 1; rel = b; }
    else if (b < 727) { li = 0; rel = b - 184; }
    else if (b < 779) { li = 2; rel = b - 727; }
    else if (b < 795) { li = 3; rel = b - 779; }
    else if (b < 801) { li = 4; rel = b - 795; }
    else              { li = 5; rel = b - 801; }

    const int C  = d_C[li];
    const int H  = d_H[li];
    const int W  = H;
    const int an = d_AN[li];
    const int aoff = d_AOFF[li];
    const int nx = d_NX[li];
    const int Mc = an * 81;
    const int M  = an * 85;
    const int HW = H * W;
    const int Ncols = NIMG * HW;
    const int K  = C * 9;            // multiple of 16 for all levels

    const float* __restrict__ feat = P.feat[li];
    const float* __restrict__ cw   = P.cw[li];
    const float* __restrict__ cb   = P.cb[li];
    const float* __restrict__ rw   = P.rw[li];
    const float* __restrict__ rb   = P.rb[li];

    extern __shared__ __align__(16) char dynsmem[];
    // As2: [stage][k][lm] float2 duplicated A ; Bs: [stage][k][lm] float
    float2* As2 = (float2*)dynsmem;                    // 4*16*128*8 = 65536 B
    float*  Bs  = (float*)(dynsmem + 65536);           // 4*16*128*4 = 32768 B
#define AS2(st, k, l) As2[((st) << 11) + ((k) << 7) + (l)]
#define BS(st, k, l)  Bs [((st) << 11) + ((k) << 7) + (l)]

    const int tid = threadIdx.x;
    const int m0  = (rel / nx) * 128;
    const int n0  = (rel % nx) * 128;

    // loader mapping: 128 lanes (lm) x 2 k-halves (lk8 = 0 or 8)
    const int lm  = tid & 127;
    const int lk8 = (tid >> 7) * 8;

    // A row pointer for this loader lane
    const int am = m0 + lm;
    const float* arow = nullptr;
    if (am < Mc)      arow = cw + (size_t)am * K;
    else if (am < M)  arow = rw + (size_t)(am - Mc) * K;

    // B column decode for this loader lane
    const int col = n0 + lm;
    const bool colv = (col < Ncols);
    int img = 0, oh = 0, ow = 0;
    if (colv) { img = col / HW; int r = col % HW; oh = r / W; ow = r % W; }
    const float* fimg = feat + (size_t)img * C * HW;

    const int ty = tid >> 4;   // 0..15 (M dir)
    const int tx = tid & 15;   // 0..15 (N dir)

    // cascaded packed accumulators: mid (FFMA2 target) + hi (flush target)
    unsigned long long accm[8][4], acch[8][4];
#pragma unroll
    for (int i = 0; i < 8; ++i)
#pragma unroll
        for (int u = 0; u < 4; ++u) { accm[i][u] = 0ull; acch[i][u] = 0ull; }

    const int nch = K >> 4;

    float pa[8], pb[8];
    // helper lambda-free prefetch of chunk c into (pa, pb)
#define PREFETCH_CHUNK(CH)                                                    \
    do {                                                                      \
        const int k0_ = (CH) << 4;                                            \
        if (arow) {                                                           \
            const float4 v0_ = *(const float4*)(arow + k0_ + lk8);            \
            const float4 v1_ = *(const float4*)(arow + k0_ + lk8 + 4);        \
            pa[0] = v0_.x; pa[1] = v0_.y; pa[2] = v0_.z; pa[3] = v0_.w;       \
            pa[4] = v1_.x; pa[5] = v1_.y; pa[6] = v1_.z; pa[7] = v1_.w;       \
        } else {                                                              \
            pa[0]=pa[1]=pa[2]=pa[3]=pa[4]=pa[5]=pa[6]=pa[7]=0.f;              \
        }                                                                     \
        _Pragma("unroll")                                                     \
        for (int u_ = 0; u_ < 8; ++u_) {                                      \
            const int k_ = k0_ + lk8 + u_;                                    \
            float v_ = 0.f;                                                   \
            if (colv) {                                                       \
                const int c_  = k_ / 9;                                       \
                const int r_  = k_ - c_ * 9;                                  \
                const int ih_ = oh + r_ / 3 - 1;                              \
                const int iw_ = ow + (r_ % 3) - 1;                            \
                if ((unsigned)ih_ < (unsigned)H && (unsigned)iw_ < (unsigned)W)\
                    v_ = fimg[((size_t)c_ * H + ih_) * W + iw_];              \
            }                                                                 \
            pb[u_] = v_;                                                      \
        }                                                                     \
    } while (0)

#define STORE_CHUNK(ST)                                                       \
    do {                                                                      \
        _Pragma("unroll")                                                     \
        for (int u_ = 0; u_ < 8; ++u_) {                                      \
            AS2(ST, lk8 + u_, lm) = make_float2(pa[u_], pa[u_]);              \
            BS (ST, lk8 + u_, lm) = pb[u_];                                   \
        }                                                                     \
    } while (0)

    // ---- prologue: fill stage 0, prefetch chunk 1 ----
    PREFETCH_CHUNK(0);
    STORE_CHUNK(0);
    if (nch > 1) PREFETCH_CHUNK(1);
    __syncthreads();

    int fcnt = 0;
    for (int ch = 0; ch < nch; ++ch) {
        // regs hold chunk ch+1: publish it a full compute-phase ahead of the
        // barrier that makes it visible (STS drain hidden under compute).
        if (ch + 1 < nch) STORE_CHUNK((ch + 1) & 3);
        if (ch + 2 < nch) PREFETCH_CHUNK(ch + 2);

        // ---- compute 16-deep chunk ch from stage ch&3 ----
        const int st = ch & 3;
#pragma unroll
        for (int kk = 0; kk < 16; ++kk) {
            const ulonglong2 a01 = *(const ulonglong2*)&AS2(st, kk, ty * 8);
            const ulonglong2 a23 = *(const ulonglong2*)&AS2(st, kk, ty * 8 + 2);
            const ulonglong2 a45 = *(const ulonglong2*)&AS2(st, kk, ty * 8 + 4);
            const ulonglong2 a67 = *(const ulonglong2*)&AS2(st, kk, ty * 8 + 6);
            const ulonglong2 b0  = *(const ulonglong2*)&BS(st, kk, tx * 8);
            const ulonglong2 b1  = *(const ulonglong2*)&BS(st, kk, tx * 8 + 4);
            const unsigned long long ap[8] =
                { a01.x, a01.y, a23.x, a23.y, a45.x, a45.y, a67.x, a67.y };
            const unsigned long long bp[4] = { b0.x, b0.y, b1.x, b1.y };
#pragma unroll
            for (int i = 0; i < 8; ++i)
#pragma unroll
                for (int u = 0; u < 4; ++u)
                    asm("fma.rn.f32x2 %0, %1, %2, %0;"
                        : "+l"(accm[i][u]) : "l"(ap[i]), "l"(bp[u]));
        }

        // ---- cascade flush every 12 chunks (192 k-values, as before) ----
        if (++fcnt == 12) {
            fcnt = 0;
#pragma unroll
            for (int i = 0; i < 8; ++i)
#pragma unroll
                for (int u = 0; u < 4; ++u) {
                    asm("add.rn.f32x2 %0, %0, %1;"
                        : "+l"(acch[i][u]) : "l"(accm[i][u]));
                    accm[i][u] = 0ull;
                }
        }
        __syncthreads();
    }

    // ---- epilogue: bias add + scatter to g_cls / g_reg ----
#pragma unroll
    for (int i = 0; i < 8; ++i) {
        const int m = m0 + ty * 8 + i;
        if (m >= M) continue;
        const float bias = (m < Mc) ? cb[m] : rb[m - Mc];
#pragma unroll
        for (int u = 0; u < 4; ++u) {
            const float lo = __uint_as_float((unsigned)(acch[i][u] & 0xFFFFFFFFull));
            const float hi = __uint_as_float((unsigned)(acch[i][u] >> 32));
#pragma unroll
            for (int half = 0; half < 2; ++half) {
                const int j  = 2 * u + half;
                const int cc = n0 + tx * 8 + j;
                if (cc >= Ncols) continue;
                const float v = (half ? hi : lo) + bias;
                const int im = cc / HW;
                const int r  = cc % HW;
                const int o_h = r / W, o_w = r - o_h * W;
                const int base = (o_h * W + o_w) * an;
                if (m < Mc) {
                    const int a = m / 81, t = m - a * 81;
                    const int anc = aoff + base + a;
                    g_cls[((size_t)im * NANCH + anc) * 81 + t] = v;
                } else {
                    const int mm = m - Mc;
                    const int a = mm >> 2, t = mm & 3;
                    const int anc = aoff + base + a;
                    g_reg[((size_t)im * NANCH + anc) * 4 + t] = v;
                }
            }
        }
    }
}

// ---------------- softmax over 81 classes, drop background, threshold ----
// fused histogram; sum in fp64 (rounded once).
__global__ void softmax_kernel()
{
    const int w    = (blockIdx.x * blockDim.x + threadIdx.x) >> 5;
    const int lane = threadIdx.x & 31;
    if (w >= NIMG * NANCH) return;
    const int img  = w / NANCH;
    const float* in = g_cls + (size_t)w * 81;
    unsigned int* h = g_hist + img * 65536;

    const float NEG = -3.0e38f;
    float v0 = in[lane];
    float v1 = (lane + 32 < 81) ? in[lane + 32] : NEG;
    float v2 = (lane + 64 < 81) ? in[lane + 64] : NEG;
    float m = fmaxf(v0, fmaxf(v1, v2));
#pragma unroll
    for (int off = 16; off > 0; off >>= 1)
        m = fmaxf(m, __shfl_xor_sync(0xFFFFFFFFu, m, off));
    float e0 = expf(v0 - m);
    float e1 = (lane + 32 < 81) ? expf(v1 - m) : 0.f;
    float e2 = (lane + 64 < 81) ? expf(v2 - m) : 0.f;
    double s = (double)e0 + (double)e1 + (double)e2;
#pragma unroll
    for (int off = 16; off > 0; off >>= 1)
        s += __shfl_xor_sync(0xFFFFFFFFu, s, off);
    const float sf = (float)s;

    float* out = g_scr + (size_t)w * NCLS;
    if (lane >= 1) {
        float p = e0 / sf;
        const bool pos = (p > 0.01f);
        out[lane - 1] = pos ? p : 0.f;
        if (pos) atomicAdd(&h[__float_as_uint(p) >> 16], 1u);
    }
    if (lane + 32 < 81) {
        float p = e1 / sf;
        const bool pos = (p > 0.01f);
        out[lane + 31] = pos ? p : 0.f;
        if (pos) atomicAdd(&h[__float_as_uint(p) >> 16], 1u);
    }
    if (lane + 64 < 81) {
        float p = e2 / sf;
        const bool pos = (p > 0.01f);
        out[lane + 63] = pos ? p : 0.f;
        if (pos) atomicAdd(&h[__float_as_uint(p) >> 16], 1u);
    }
}

// ---------------- find boundary bucket (suffix count >= 400) ----------------
__global__ void __launch_bounds__(1024) boundary_kernel()
{
    __shared__ unsigned int cs[1024];
    const int img = blockIdx.x, t = threadIdx.x;
    const unsigned int* h = g_hist + img * 65536;
    unsigned int s = 0;
    const int base = t * 64;
    for (int b = 0; b < 64; ++b) s += h[base + b];
    cs[t] = s;
    __syncthreads();
    if (t == 0) {
        unsigned int acc = 0, thr = 0;
        int chunk = -1;
        for (int c = 1023; c >= 0; --c) {
            if (acc + cs[c] >= NCAND) { chunk = c; break; }
            acc += cs[c];
        }
        if (chunk >= 0) {
            for (int b = chunk * 64 + 63; b >= chunk * 64; --b) {
                acc += h[b];
                if (acc >= NCAND) { thr = (unsigned)b; break; }
            }
        }
        g_thr[img] = thr;
        g_cnt[img] = 0;
    }
}

// ---------------- collect top-400 superset ----------------
__global__ void collect_kernel()
{
    const int img = blockIdx.y;
    const unsigned int thr = g_thr[img];
    const float* f = g_scr + (size_t)img * FLATC;
    for (int j = blockIdx.x * blockDim.x + threadIdx.x; j < FLATC;
         j += gridDim.x * blockDim.x) {
        const float v = f[j];
        if (v > 0.f && (__float_as_uint(v) >> 16) >= thr) {
            const int p = atomicAdd(&g_cnt[img], 1);
            if (p < CAP) {
                g_cand_v[img * CAP + p] = v;
                g_cand_i[img * CAP + p] = j;
            }
        }
    }
}

// ---------------- bitonic sort (desc by value, asc by index on ties) ------
__global__ void __launch_bounds__(512) sort_kernel()
{
    __shared__ unsigned long long keys[CAP];
    const int img = blockIdx.x, tid = threadIdx.x;
    int n = g_cnt[img];
    if (n > CAP) n = CAP;

    for (int i = tid; i < CAP; i += 512) {
        unsigned long long key = 0ull;
        if (i < n) {
            const unsigned vb = __float_as_uint(g_cand_v[img * CAP + i]);
            const unsigned ix = (unsigned)g_cand_i[img * CAP + i];
            key = ((unsigned long long)vb << 32) | (0xFFFFFFFFu - ix);
        }
        keys[i] = key;
    }
    __syncthreads();

    for (int k = 2; k <= CAP; k <<= 1) {
        for (int j = k >> 1; j > 0; j >>= 1) {
            for (int i = tid; i < CAP; i += 512) {
                const int ixj = i ^ j;
                if (ixj > i) {
                    const bool desc = ((i & k) == 0);
                    const unsigned long long a = keys[i], b = keys[ixj];
                    if (desc ? (a < b) : (a > b)) { keys[i] = b; keys[ixj] = a; }
                }
            }
            __syncthreads();
        }
    }

    if (tid < NCAND) {
        const unsigned long long key = keys[tid];
        g_top_v[img * NCAND + tid] = __uint_as_float((unsigned)(key >> 32));
        g_top_i[img * NCAND + tid] = (int)(0xFFFFFFFFu - (unsigned)(key & 0xFFFFFFFFull));
    }
    __syncthreads();
    // padding path: fewer than 400 positives -> lax.top_k fills with the
    // lowest-index zero entries
    if (tid == 0 && n < NCAND) {
        const float* f = g_scr + (size_t)img * FLATC;
        int p = n;
        for (int j = 0; j < FLATC && p < NCAND; ++j) {
            if (f[j] == 0.0f) {
                g_top_v[img * NCAND + p] = 0.f;
                g_top_i[img * NCAND + p] = j;
                ++p;
            }
        }
    }
}

// ---------------- decode + class-aware NMS + final top-200 ----------------
__global__ void __launch_bounds__(512)
postnms_kernel(const float* __restrict__ priors, float* __restrict__ out)
{
    __shared__ float sx1[NCAND], sy1[NCAND], sx2[NCAND], sy2[NCAND];
    __shared__ float ox1[NCAND], oy1[NCAND], ox2[NCAND], oy2[NCAND], oar[NCAND];
    __shared__ float s_sc[NCAND];
    __shared__ int   s_cls[NCAND], s_keep[NCAND];
    __shared__ int   s_fi[NOUT];

    const int img = blockIdx.x, tid = threadIdx.x;

    if (tid < NCAND) {
        const float v  = g_top_v[img * NCAND + tid];
        const int idx  = g_top_i[img * NCAND + tid];
        const int cls  = idx % NCLS + 1;
        const int anc  = idx / NCLS;
        const float* d = g_reg + ((size_t)img * NANCH + anc) * 4;
        const float* p = priors + (size_t)anc * 4;
        const float cx = p[0] + d[0] * 0.1f * p[2];
        const float cy = p[1] + d[1] * 0.1f * p[3];
        const float w  = p[2] * expf(fminf(d[2] * 0.2f, CLIPV));
        const float h  = p[3] * expf(fminf(d[3] * 0.2f, CLIPV));
        float x1 = cx - 0.5f * w, y1 = cy - 0.5f * h;
        float x2 = cx + 0.5f * w, y2 = cy + 0.5f * h;
        x1 = fminf(fmaxf(x1, 0.f), 300.f);
        y1 = fminf(fmaxf(y1, 0.f), 300.f);
        x2 = fminf(fmaxf(x2, 0.f), 300.f);
        y2 = fminf(fmaxf(y2, 0.f), 300.f);
        const bool valid = (v > 0.f) && (x2 > x1) && (y2 > y1);
        sx1[tid] = x1; sy1[tid] = y1; sx2[tid] = x2; sy2[tid] = y2;
        s_sc[tid] = valid ? v : 0.f;
        s_cls[tid] = cls;
        s_keep[tid] = valid ? 1 : 0;
        // class offset applied BEFORE area/IoU, exactly as in the reference
        const float off = (float)cls * 301.0f;
        const float a1 = x1 + off, b1 = y1 + off, a2 = x2 + off, b2 = y2 + off;
        ox1[tid] = a1; oy1[tid] = b1; ox2[tid] = a2; oy2[tid] = b2;
        oar[tid] = (a2 - a1) * (b2 - b1);
    }
    __syncthreads();

    // greedy NMS, iteration order identical to the fori_loop
    for (int i = 0; i < NCAND; ++i) {
        if (s_keep[i]) {
            const int j = tid;
            if (j > i && j < NCAND && s_keep[j]) {
                const float ltx = fmaxf(ox1[i], ox1[j]);
                const float lty = fmaxf(oy1[i], oy1[j]);
                const float rbx = fminf(ox2[i], ox2[j]);
                const float rby = fminf(oy2[i], oy2[j]);
                const float ww = fmaxf(rbx - ltx, 0.f);
                const float hh = fmaxf(rby - lty, 0.f);
                const float inter = ww * hh;
                const float iou = inter / (oar[i] + oar[j] - inter + 1e-9f);
                if (iou > 0.45f) s_keep[j] = 0;
            }
        }
        __syncthreads();
    }

    // final top_k(where(keep, s, 0), 200):
    // kept positions ascending (s is already sorted desc), then zero-valued
    // (non-kept) positions ascending -- matches value-desc/index-asc ties.
    if (tid == 0) {
        int p = 0;
        for (int i = 0; i < NCAND && p < NOUT; ++i) if (s_keep[i])  s_fi[p++] = i;
        for (int i = 0; i < NCAND && p < NOUT; ++i) if (!s_keep[i]) s_fi[p++] = i;
    }
    __syncthreads();

    if (tid < NOUT) {
        const int o = s_fi[tid];
        const float fsv = s_keep[o] ? s_sc[o] : 0.f;
        const size_t bo = ((size_t)img * NOUT + tid) * 4;
        out[bo + 0] = sx1[o];
        out[bo + 1] = sy1[o];
        out[bo + 2] = sx2[o];
        out[bo + 3] = sy2[o];
        out[(size_t)NIMG * NOUT * 4 + img * NOUT + tid] = fsv;
        out[(size_t)NIMG * NOUT * 5 + img * NOUT + tid] =
            (fsv > 0.f) ? (float)s_cls[o] : 0.f;
    }
}

// ---------------- host launch ----------------
extern "C" void kernel_launch(void* const* d_in, const int* in_sizes, int n_in,
                              void* d_out, int out_size)
{
    (void)out_size;
    // input-order detection: signature order has feat1 (5,914,624 elems) at
    // slot 1; dict-insertion order has cls_w0 (1,492,992) there.
    const bool sig = (n_in > 1 && in_sizes[1] == 16 * 1024 * 19 * 19);
    int fI[6], cwI[6], cbI[6], rwI[6], rbI[6];
    for (int i = 0; i < 6; ++i) {
        if (sig) {
            fI[i] = i;
            cwI[i] = 6 + 2 * i;  cbI[i] = 7 + 2 * i;
            rwI[i] = 18 + 2 * i; rbI[i] = 19 + 2 * i;
        } else {
            fI[i] = 5 * i;
            cwI[i] = 5 * i + 1; cbI[i] = 5 * i + 2;
            rwI[i] = 5 * i + 3; rbI[i] = 5 * i + 4;
        }
    }
    const float* priors = (const float*)d_in[30];
    float* out = (float*)d_out;

    HeadPtrs P;
    for (int i = 0; i < 6; ++i) {
        P.feat[i] = (const float*)d_in[fI[i]];
        P.cw[i]   = (const float*)d_in[cwI[i]];
        P.cb[i]   = (const float*)d_in[cbI[i]];
        P.rw[i]   = (const float*)d_in[rwI[i]];
        P.rb[i]   = (const float*)d_in[rbI[i]];
    }

    static bool attr_set = false;
    if (!attr_set) {
        cudaFuncSetAttribute(head_gemm_all,
                             cudaFuncAttributeMaxDynamicSharedMemorySize,
                             GEMM_SMEM);
        attr_set = true;
    }

    zero_kernel<<<512, 256>>>();

    // single merged launch: 184(L1) + 543(L0) + 52(L2) + 16(L3) + 6(L4) + 3(L5)
    head_gemm_all<<<804, 256, GEMM_SMEM>>>(P);

    softmax_kernel<<<(NIMG * NANCH + 7) / 8, 256>>>();   // hist fused in
    boundary_kernel<<<NIMG, 1024>>>();
    collect_kernel<<<dim3(256, NIMG), 256>>>();
    sort_kernel<<<NIMG, 512>>>();
    postnms_kernel<<<NIMG, 512>>>(priors, out);
}

// round 12
// speedup vs baseline: 1.0411x; 1.0411x over previous
#include <cuda_runtime.h>
#include <cuda_bf16.h>
#include <math.h>
#include <stdint.h>

#define NIMG   16
#define NANCH  8732
#define NCLS   80
#define FLATC  (NANCH * NCLS)     // 698560
#define NCAND  400
#define NOUT   200
#define CAP    4096
#define CLIPV  4.135166556742356f // log(1000/16)

// ---------------- device scratch (no allocations allowed) ----------------
__device__ float        g_cls[(size_t)NIMG * NANCH * 81];   // logits
__device__ float        g_scr[(size_t)NIMG * FLATC];        // thresholded softmax scores
__device__ float        g_reg[(size_t)NIMG * NANCH * 4];    // box deltas
__device__ unsigned int g_hist[NIMG * 65536];
__device__ int          g_cnt[NIMG];
__device__ unsigned int g_thr[NIMG];
__device__ float        g_cand_v[NIMG * CAP];
__device__ int          g_cand_i[NIMG * CAP];
__device__ float        g_top_v[NIMG * NCAND];
__device__ int          g_top_i[NIMG * NCAND];

// ---------------- zero histograms ----------------
__global__ void zero_kernel()
{
    int i  = blockIdx.x * blockDim.x + threadIdx.x;
    int st = gridDim.x * blockDim.x;
    for (int t = i; t < NIMG * 65536; t += st) g_hist[t] = 0u;
}

// ---------------- merged fused cls+reg conv heads: ONE launch -------------
// Round-8 skeleton (proven best): 804-CTA merged grid, 256 threads,
// 128x128x16 tile, 8Mx8N microtile, 2-stage static smem, store->bar->
// prefetch->compute. NEW: explicit kk-level register double-buffering of
// the A/B fragments so the 6 LDS.128 of step kk+1 issue before the 32
// FFMA2 of step kk -> hides the 29-cyc LDS latency with only 2 warps/SMSP.
// FFMA2 order per accumulator unchanged -> bitwise-identical results.
struct HeadPtrs {
    const float* feat[6];
    const float* cw[6];
    const float* cb[6];
    const float* rw[6];
    const float* rb[6];
};

__device__ __constant__ int d_C[6]    = {512, 1024, 512, 256, 256, 256};
__device__ __constant__ int d_H[6]    = {38, 19, 10, 5, 3, 1};
__device__ __constant__ int d_AN[6]   = {4, 6, 6, 6, 4, 4};
__device__ __constant__ int d_AOFF[6] = {0, 5776, 7942, 8542, 8692, 8728};
__device__ __constant__ int d_NX[6]   = {181, 46, 13, 4, 2, 1};  // ceil(Nc/128)

__global__ void __launch_bounds__(256, 1)
head_gemm_all(const HeadPtrs P)
{
    // ---- block -> (level, tile) mapping; work-heavy levels first ----
    const int b = blockIdx.x;
    int li, rel;
    if      (b < 184) { li = 1; rel = b; }
    else if (b < 727) { li = 0; rel = b - 184; }
    else if (b < 779) { li = 2; rel = b - 727; }
    else if (b < 795) { li = 3; rel = b - 779; }
    else if (b < 801) { li = 4; rel = b - 795; }
    else              { li = 5; rel = b - 801; }

    const int C  = d_C[li];
    const int H  = d_H[li];
    const int W  = H;
    const int an = d_AN[li];
    const int aoff = d_AOFF[li];
    const int nx = d_NX[li];
    const int Mc = an * 81;
    const int M  = an * 85;
    const int HW = H * W;
    const int Ncols = NIMG * HW;
    const int K  = C * 9;            // multiple of 16 for all levels

    const float* __restrict__ feat = P.feat[li];
    const float* __restrict__ cw   = P.cw[li];
    const float* __restrict__ cb   = P.cb[li];
    const float* __restrict__ rw   = P.rw[li];
    const float* __restrict__ rb   = P.rb[li];

    __shared__ __align__(16) float2 As2[2][16][128];   // duplicated A
    __shared__ __align__(16) float  Bs[2][16][128];

    const int tid = threadIdx.x;
    const int m0  = (rel / nx) * 128;
    const int n0  = (rel % nx) * 128;

    // loader mapping: 128 lanes (lm) x 2 k-halves (lk8 = 0 or 8)
    const int lm  = tid & 127;
    const int lk8 = (tid >> 7) * 8;

    // A row pointer for this loader lane
    const int am = m0 + lm;
    const float* arow = nullptr;
    if (am < Mc)      arow = cw + (size_t)am * K;
    else if (am < M)  arow = rw + (size_t)(am - Mc) * K;

    // B column decode for this loader lane
    const int col = n0 + lm;
    const bool colv = (col < Ncols);
    int img = 0, oh = 0, ow = 0;
    if (colv) { img = col / HW; int r = col % HW; oh = r / W; ow = r % W; }
    const float* fimg = feat + (size_t)img * C * HW;

    const int ty = tid >> 4;   // 0..15 (M dir)
    const int tx = tid & 15;   // 0..15 (N dir)

    // cascaded packed accumulators: mid (FFMA2 target) + hi (flush target)
    unsigned long long accm[8][4], acch[8][4];
#pragma unroll
    for (int i = 0; i < 8; ++i)
#pragma unroll
        for (int u = 0; u < 4; ++u) { accm[i][u] = 0ull; acch[i][u] = 0ull; }

    const int nch = K >> 4;

    // ---- prefetch chunk 0 into registers ----
    float pa[8], pb[8];
    {
#pragma unroll
        for (int u = 0; u < 8; ++u) pa[u] = 0.f;
        if (arow) {
            const float4 v0 = *(const float4*)(arow + lk8);
            const float4 v1 = *(const float4*)(arow + lk8 + 4);
            pa[0] = v0.x; pa[1] = v0.y; pa[2] = v0.z; pa[3] = v0.w;
            pa[4] = v1.x; pa[5] = v1.y; pa[6] = v1.z; pa[7] = v1.w;
        }
#pragma unroll
        for (int u = 0; u < 8; ++u) {
            const int k = lk8 + u;
            float v = 0.f;
            if (colv) {
                const int c  = k / 9;
                const int r  = k - c * 9;
                const int ih = oh + r / 3 - 1;
                const int iw = ow + (r % 3) - 1;
                if ((unsigned)ih < (unsigned)H && (unsigned)iw < (unsigned)W)
                    v = fimg[((size_t)c * H + ih) * W + iw];
            }
            pb[u] = v;
        }
    }

    int fcnt = 0;
    int cur  = 0;
    for (int ch = 0; ch < nch; ++ch) {
        // ---- commit prefetched chunk to smem[cur] ----
#pragma unroll
        for (int u = 0; u < 8; ++u) {
            As2[cur][lk8 + u][lm] = make_float2(pa[u], pa[u]);
            Bs [cur][lk8 + u][lm] = pb[u];
        }
        __syncthreads();

        // ---- issue prefetch of next chunk (overlaps with compute) ----
        if (ch + 1 < nch) {
            const int k0 = (ch + 1) << 4;
            if (arow) {
                const float4 v0 = *(const float4*)(arow + k0 + lk8);
                const float4 v1 = *(const float4*)(arow + k0 + lk8 + 4);
                pa[0] = v0.x; pa[1] = v0.y; pa[2] = v0.z; pa[3] = v0.w;
                pa[4] = v1.x; pa[5] = v1.y; pa[6] = v1.z; pa[7] = v1.w;
            }
#pragma unroll
            for (int u = 0; u < 8; ++u) {
                const int k = k0 + lk8 + u;
                float v = 0.f;
                if (colv) {
                    const int c  = k / 9;
                    const int r  = k - c * 9;
                    const int ih = oh + r / 3 - 1;
                    const int iw = ow + (r % 3) - 1;
                    if ((unsigned)ih < (unsigned)H && (unsigned)iw < (unsigned)W)
                        v = fimg[((size_t)c * H + ih) * W + iw];
                }
                pb[u] = v;
            }
        }

        // ---- compute 16-deep chunk from smem[cur] with register double ----
        // ---- buffering of the per-kk fragments                        ----
        {
            ulonglong2 Ar[2][4];
            ulonglong2 Br[2][2];
            // preload kk = 0 into buffer 0
            Ar[0][0] = *(const ulonglong2*)&As2[cur][0][ty * 8];
            Ar[0][1] = *(const ulonglong2*)&As2[cur][0][ty * 8 + 2];
            Ar[0][2] = *(const ulonglong2*)&As2[cur][0][ty * 8 + 4];
            Ar[0][3] = *(const ulonglong2*)&As2[cur][0][ty * 8 + 6];
            Br[0][0] = *(const ulonglong2*)&Bs[cur][0][tx * 8];
            Br[0][1] = *(const ulonglong2*)&Bs[cur][0][tx * 8 + 4];
#pragma unroll
            for (int kk = 0; kk < 16; ++kk) {
                const int cb_ = kk & 1;
                const int nb_ = cb_ ^ 1;
                if (kk < 15) {
                    Ar[nb_][0] = *(const ulonglong2*)&As2[cur][kk + 1][ty * 8];
                    Ar[nb_][1] = *(const ulonglong2*)&As2[cur][kk + 1][ty * 8 + 2];
                    Ar[nb_][2] = *(const ulonglong2*)&As2[cur][kk + 1][ty * 8 + 4];
                    Ar[nb_][3] = *(const ulonglong2*)&As2[cur][kk + 1][ty * 8 + 6];
                    Br[nb_][0] = *(const ulonglong2*)&Bs[cur][kk + 1][tx * 8];
                    Br[nb_][1] = *(const ulonglong2*)&Bs[cur][kk + 1][tx * 8 + 4];
                }
                const unsigned long long ap[8] =
                    { Ar[cb_][0].x, Ar[cb_][0].y, Ar[cb_][1].x, Ar[cb_][1].y,
                      Ar[cb_][2].x, Ar[cb_][2].y, Ar[cb_][3].x, Ar[cb_][3].y };
                const unsigned long long bp[4] =
                    { Br[cb_][0].x, Br[cb_][0].y, Br[cb_][1].x, Br[cb_][1].y };
#pragma unroll
                for (int i = 0; i < 8; ++i)
#pragma unroll
                    for (int u = 0; u < 4; ++u)
                        asm("fma.rn.f32x2 %0, %1, %2, %0;"
                            : "+l"(accm[i][u]) : "l"(ap[i]), "l"(bp[u]));
            }
        }

        // ---- cascade flush every 12 chunks (192 k-values, as before) ----
        if (++fcnt == 12) {
            fcnt = 0;
#pragma unroll
            for (int i = 0; i < 8; ++i)
#pragma unroll
                for (int u = 0; u < 4; ++u) {
                    asm("add.rn.f32x2 %0, %0, %1;"
                        : "+l"(acch[i][u]) : "l"(accm[i][u]));
                    accm[i][u] = 0ull;
                }
        }
        cur ^= 1;
    }

    // ---- epilogue: bias add + scatter to g_cls / g_reg ----
#pragma unroll
    for (int i = 0; i < 8; ++i) {
        const int m = m0 + ty * 8 + i;
        if (m >= M) continue;
        const float bias = (m < Mc) ? cb[m] : rb[m - Mc];
#pragma unroll
        for (int u = 0; u < 4; ++u) {
            const float lo = __uint_as_float((unsigned)(acch[i][u] & 0xFFFFFFFFull));
            const float hi = __uint_as_float((unsigned)(acch[i][u] >> 32));
#pragma unroll
            for (int half = 0; half < 2; ++half) {
                const int j  = 2 * u + half;
                const int cc = n0 + tx * 8 + j;
                if (cc >= Ncols) continue;
                const float v = (half ? hi : lo) + bias;
                const int im = cc / HW;
                const int r  = cc % HW;
                const int o_h = r / W, o_w = r - o_h * W;
                const int base = (o_h * W + o_w) * an;
                if (m < Mc) {
                    const int a = m / 81, t = m - a * 81;
                    const int anc = aoff + base + a;
                    g_cls[((size_t)im * NANCH + anc) * 81 + t] = v;
                } else {
                    const int mm = m - Mc;
                    const int a = mm >> 2, t = mm & 3;
                    const int anc = aoff + base + a;
                    g_reg[((size_t)im * NANCH + anc) * 4 + t] = v;
                }
            }
        }
    }
}

// ---------------- softmax over 81 classes, drop background, threshold ----
// fused histogram; sum in fp64 (rounded once).
__global__ void softmax_kernel()
{
    const int w    = (blockIdx.x * blockDim.x + threadIdx.x) >> 5;
    const int lane = threadIdx.x & 31;
    if (w >= NIMG * NANCH) return;
    const int img  = w / NANCH;
    const float* in = g_cls + (size_t)w * 81;
    unsigned int* h = g_hist + img * 65536;

    const float NEG = -3.0e38f;
    float v0 = in[lane];
    float v1 = (lane + 32 < 81) ? in[lane + 32] : NEG;
    float v2 = (lane + 64 < 81) ? in[lane + 64] : NEG;
    float m = fmaxf(v0, fmaxf(v1, v2));
#pragma unroll
    for (int off = 16; off > 0; off >>= 1)
        m = fmaxf(m, __shfl_xor_sync(0xFFFFFFFFu, m, off));
    float e0 = expf(v0 - m);
    float e1 = (lane + 32 < 81) ? expf(v1 - m) : 0.f;
    float e2 = (lane + 64 < 81) ? expf(v2 - m) : 0.f;
    double s = (double)e0 + (double)e1 + (double)e2;
#pragma unroll
    for (int off = 16; off > 0; off >>= 1)
        s += __shfl_xor_sync(0xFFFFFFFFu, s, off);
    const float sf = (float)s;

    float* out = g_scr + (size_t)w * NCLS;
    if (lane >= 1) {
        float p = e0 / sf;
        const bool pos = (p > 0.01f);
        out[lane - 1] = pos ? p : 0.f;
        if (pos) atomicAdd(&h[__float_as_uint(p) >> 16], 1u);
    }
    if (lane + 32 < 81) {
        float p = e1 / sf;
        const bool pos = (p > 0.01f);
        out[lane + 31] = pos ? p : 0.f;
        if (pos) atomicAdd(&h[__float_as_uint(p) >> 16], 1u);
    }
    if (lane + 64 < 81) {
        float p = e2 / sf;
        const bool pos = (p > 0.01f);
        out[lane + 63] = pos ? p : 0.f;
        if (pos) atomicAdd(&h[__float_as_uint(p) >> 16], 1u);
    }
}

// ---------------- find boundary bucket (suffix count >= 400) ----------------
__global__ void boundary_kernel()
{
    __shared__ unsigned int cs[256];
    const int img = blockIdx.x, t = threadIdx.x;
    const unsigned int* h = g_hist + img * 65536;
    unsigned int s = 0;
    const int base = t * 256;
    for (int b = 0; b < 256; ++b) s += h[base + b];
    cs[t] = s;
    __syncthreads();
    if (t == 0) {
        unsigned int acc = 0, thr = 0;
        int chunk = -1;
        for (int c = 255; c >= 0; --c) {
            if (acc + cs[c] >= NCAND) { chunk = c; break; }
            acc += cs[c];
        }
        if (chunk >= 0) {
            for (int b = chunk * 256 + 255; b >= chunk * 256; --b) {
                acc += h[b];
                if (acc >= NCAND) { thr = (unsigned)b; break; }
            }
        }
        g_thr[img] = thr;
        g_cnt[img] = 0;
    }
}

// ---------------- collect top-400 superset ----------------
__global__ void collect_kernel()
{
    const int img = blockIdx.y;
    const unsigned int thr = g_thr[img];
    const float* f = g_scr + (size_t)img * FLATC;
    for (int j = blockIdx.x * blockDim.x + threadIdx.x; j < FLATC;
         j += gridDim.x * blockDim.x) {
        const float v = f[j];
        if (v > 0.f && (__float_as_uint(v) >> 16) >= thr) {
            const int p = atomicAdd(&g_cnt[img], 1);
            if (p < CAP) {
                g_cand_v[img * CAP + p] = v;
                g_cand_i[img * CAP + p] = j;
            }
        }
    }
}

// ---------------- bitonic sort (desc by value, asc by index on ties) ------
__global__ void __launch_bounds__(512) sort_kernel()
{
    __shared__ unsigned long long keys[CAP];
    const int img = blockIdx.x, tid = threadIdx.x;
    int n = g_cnt[img];
    if (n > CAP) n = CAP;

    for (int i = tid; i < CAP; i += 512) {
        unsigned long long key = 0ull;
        if (i < n) {
            const unsigned vb = __float_as_uint(g_cand_v[img * CAP + i]);
            const unsigned ix = (unsigned)g_cand_i[img * CAP + i];
            key = ((unsigned long long)vb << 32) | (0xFFFFFFFFu - ix);
        }
        keys[i] = key;
    }
    __syncthreads();

    for (int k = 2; k <= CAP; k <<= 1) {
        for (int j = k >> 1; j > 0; j >>= 1) {
            for (int i = tid; i < CAP; i += 512) {
                const int ixj = i ^ j;
                if (ixj > i) {
                    const bool desc = ((i & k) == 0);
                    const unsigned long long a = keys[i], b = keys[ixj];
                    if (desc ? (a < b) : (a > b)) { keys[i] = b; keys[ixj] = a; }
                }
            }
            __syncthreads();
        }
    }

    if (tid < NCAND) {
        const unsigned long long key = keys[tid];
        g_top_v[img * NCAND + tid] = __uint_as_float((unsigned)(key >> 32));
        g_top_i[img * NCAND + tid] = (int)(0xFFFFFFFFu - (unsigned)(key & 0xFFFFFFFFull));
    }
    __syncthreads();
    // padding path: fewer than 400 positives -> lax.top_k fills with the
    // lowest-index zero entries
    if (tid == 0 && n < NCAND) {
        const float* f = g_scr + (size_t)img * FLATC;
        int p = n;
        for (int j = 0; j < FLATC && p < NCAND; ++j) {
            if (f[j] == 0.0f) {
                g_top_v[img * NCAND + p] = 0.f;
                g_top_i[img * NCAND + p] = j;
                ++p;
            }
        }
    }
}

// ---------------- decode + class-aware NMS + final top-200 ----------------
__global__ void __launch_bounds__(512)
postnms_kernel(const float* __restrict__ priors, float* __restrict__ out)
{
    __shared__ float sx1[NCAND], sy1[NCAND], sx2[NCAND], sy2[NCAND];
    __shared__ float ox1[NCAND], oy1[NCAND], ox2[NCAND], oy2[NCAND], oar[NCAND];
    __shared__ float s_sc[NCAND];
    __shared__ int   s_cls[NCAND], s_keep[NCAND];
    __shared__ int   s_fi[NOUT];

    const int img = blockIdx.x, tid = threadIdx.x;

    if (tid < NCAND) {
        const float v  = g_top_v[img * NCAND + tid];
        const int idx  = g_top_i[img * NCAND + tid];
        const int cls  = idx % NCLS + 1;
        const int anc  = idx / NCLS;
        const float* d = g_reg + ((size_t)img * NANCH + anc) * 4;
        const float* p = priors + (size_t)anc * 4;
        const float cx = p[0] + d[0] * 0.1f * p[2];
        const float cy = p[1] + d[1] * 0.1f * p[3];
        const float w  = p[2] * expf(fminf(d[2] * 0.2f, CLIPV));
        const float h  = p[3] * expf(fminf(d[3] * 0.2f, CLIPV));
        float x1 = cx - 0.5f * w, y1 = cy - 0.5f * h;
        float x2 = cx + 0.5f * w, y2 = cy + 0.5f * h;
        x1 = fminf(fmaxf(x1, 0.f), 300.f);
        y1 = fminf(fmaxf(y1, 0.f), 300.f);
        x2 = fminf(fmaxf(x2, 0.f), 300.f);
        y2 = fminf(fmaxf(y2, 0.f), 300.f);
        const bool valid = (v > 0.f) && (x2 > x1) && (y2 > y1);
        sx1[tid] = x1; sy1[tid] = y1; sx2[tid] = x2; sy2[tid] = y2;
        s_sc[tid] = valid ? v : 0.f;
        s_cls[tid] = cls;
        s_keep[tid] = valid ? 1 : 0;
        // class offset applied BEFORE area/IoU, exactly as in the reference
        const float off = (float)cls * 301.0f;
        const float a1 = x1 + off, b1 = y1 + off, a2 = x2 + off, b2 = y2 + off;
        ox1[tid] = a1; oy1[tid] = b1; ox2[tid] = a2; oy2[tid] = b2;
        oar[tid] = (a2 - a1) * (b2 - b1);
    }
    __syncthreads();

    // greedy NMS, iteration order identical to the fori_loop
    for (int i = 0; i < NCAND; ++i) {
        if (s_keep[i]) {
            const int j = tid;
            if (j > i && j < NCAND && s_keep[j]) {
                const float ltx = fmaxf(ox1[i], ox1[j]);
                const float lty = fmaxf(oy1[i], oy1[j]);
                const float rbx = fminf(ox2[i], ox2[j]);
                const float rby = fminf(oy2[i], oy2[j]);
                const float ww = fmaxf(rbx - ltx, 0.f);
                const float hh = fmaxf(rby - lty, 0.f);
                const float inter = ww * hh;
                const float iou = inter / (oar[i] + oar[j] - inter + 1e-9f);
                if (iou > 0.45f) s_keep[j] = 0;
            }
        }
        __syncthreads();
    }

    // final top_k(where(keep, s, 0), 200):
    // kept positions ascending (s is already sorted desc), then zero-valued
    // (non-kept) positions ascending -- matches value-desc/index-asc ties.
    if (tid == 0) {
        int p = 0;
        for (int i = 0; i < NCAND && p < NOUT; ++i) if (s_keep[i])  s_fi[p++] = i;
        for (int i = 0; i < NCAND && p < NOUT; ++i) if (!s_keep[i]) s_fi[p++] = i;
    }
    __syncthreads();

    if (tid < NOUT) {
        const int o = s_fi[tid];
        const float fsv = s_keep[o] ? s_sc[o] : 0.f;
        const size_t bo = ((size_t)img * NOUT + tid) * 4;
        out[bo + 0] = sx1[o];
        out[bo + 1] = sy1[o];
        out[bo + 2] = sx2[o];
        out[bo + 3] = sy2[o];
        out[(size_t)NIMG * NOUT * 4 + img * NOUT + tid] = fsv;
        out[(size_t)NIMG * NOUT * 5 + img * NOUT + tid] =
            (fsv > 0.f) ? (float)s_cls[o] : 0.f;
    }
}

// ---------------- host launch ----------------
extern "C" void kernel_launch(void* const* d_in, const int* in_sizes, int n_in,
                              void* d_out, int out_size)
{
    (void)out_size;
    // input-order detection: signature order has feat1 (5,914,624 elems) at
    // slot 1; dict-insertion order has cls_w0 (1,492,992) there.
    const bool sig = (n_in > 1 && in_sizes[1] == 16 * 1024 * 19 * 19);
    int fI[6], cwI[6], cbI[6], rwI[6], rbI[6];
    for (int i = 0; i < 6; ++i) {
        if (sig) {
            fI[i] = i;
            cwI[i] = 6 + 2 * i;  cbI[i] = 7 + 2 * i;
            rwI[i] = 18 + 2 * i; rbI[i] = 19 + 2 * i;
        } else {
            fI[i] = 5 * i;
            cwI[i] = 5 * i + 1; cbI[i] = 5 * i + 2;
            rwI[i] = 5 * i + 3; rbI[i] = 5 * i + 4;
        }
    }
    const float* priors = (const float*)d_in[30];
    float* out = (float*)d_out;

    HeadPtrs P;
    for (int i = 0; i < 6; ++i) {
        P.feat[i] = (const float*)d_in[fI[i]];
        P.cw[i]   = (const float*)d_in[cwI[i]];
        P.cb[i]   = (const float*)d_in[cbI[i]];
        P.rw[i]   = (const float*)d_in[rwI[i]];
        P.rb[i]   = (const float*)d_in[rbI[i]];
    }

    zero_kernel<<<512, 256>>>();

    // single merged launch: 184(L1) + 543(L0) + 52(L2) + 16(L3) + 6(L4) + 3(L5)
    head_gemm_all<<<804, 256>>>(P);

    softmax_kernel<<<(NIMG * NANCH + 7) / 8, 256>>>();   // hist fused in
    boundary_kernel<<<NIMG, 256>>>();
    collect_kernel<<<dim3(256, NIMG), 256>>>();
    sort_kernel<<<NIMG, 512>>>();
    postnms_kernel<<<NIMG, 512>>>(priors, out);
}

// round 13
// speedup vs baseline: 1.0838x; 1.0410x over previous
#include <cuda_runtime.h>
#include <cuda_bf16.h>
#include <math.h>
#include <stdint.h>

#define NIMG   16
#define NANCH  8732
#define NCLS   80
#define FLATC  (NANCH * NCLS)     // 698560
#define NCAND  400
#define NOUT   200
#define CAP    4096
#define CLIPV  4.135166556742356f // log(1000/16)

// ---------------- device scratch (no allocations allowed) ----------------
__device__ float        g_cls[(size_t)NIMG * NANCH * 81];   // logits
__device__ float        g_scr[(size_t)NIMG * FLATC];        // thresholded softmax scores
__device__ float        g_reg[(size_t)NIMG * NANCH * 4];    // box deltas
__device__ unsigned int g_hist[NIMG * 65536];
__device__ int          g_cnt[NIMG];
__device__ unsigned int g_thr[NIMG];
__device__ float        g_cand_v[NIMG * CAP];
__device__ int          g_cand_i[NIMG * CAP];
__device__ float        g_top_v[NIMG * NCAND];
__device__ int          g_top_i[NIMG * NCAND];

// ---------------- zero histograms ----------------
__global__ void zero_kernel()
{
    int i  = blockIdx.x * blockDim.x + threadIdx.x;
    int st = gridDim.x * blockDim.x;
    for (int t = i; t < NIMG * 65536; t += st) g_hist[t] = 0u;
}

// ---------------- merged fused cls+reg conv heads: ONE launch -------------
// NEW: 128-thread CTAs on 128M x 64N x 16K tiles, __launch_bounds__(128,2)
// -> 2 independent CTAs per SM. Per-SMSP warp count stays 2, but the warps
// belong to different CTAs with independent barriers, so one CTA's
// barrier-arrival/ LDS-ramp stall is covered by the other CTA's FFMA2s.
// Inner loop and per-output k-order/cascade grouping identical to the
// proven round-8 kernel -> bitwise-identical results.
struct HeadPtrs {
    const float* feat[6];
    const float* cw[6];
    const float* cb[6];
    const float* rw[6];
    const float* rb[6];
};

__device__ __constant__ int d_C[6]    = {512, 1024, 512, 256, 256, 256};
__device__ __constant__ int d_H[6]    = {38, 19, 10, 5, 3, 1};
__device__ __constant__ int d_AN[6]   = {4, 6, 6, 6, 4, 4};
__device__ __constant__ int d_AOFF[6] = {0, 5776, 7942, 8542, 8692, 8728};
__device__ __constant__ int d_NX[6]   = {361, 91, 25, 7, 3, 1};  // ceil(Nc/64)

// CTA counts per level (nx * ny, ny = ceil(M/128)): L0 1083, L1 364, L2 100,
// L3 28, L4 9, L5 3.  Order: L1, L0, L2, L3, L4, L5.
#define GRID_TOTAL 1587

__global__ void __launch_bounds__(128, 2)
head_gemm_all(const HeadPtrs P)
{
    // ---- block -> (level, tile) mapping; work-heavy levels first ----
    const int b = blockIdx.x;
    int li, rel;
    if      (b < 364)  { li = 1; rel = b; }
    else if (b < 1447) { li = 0; rel = b - 364; }
    else if (b < 1547) { li = 2; rel = b - 1447; }
    else if (b < 1575) { li = 3; rel = b - 1547; }
    else if (b < 1584) { li = 4; rel = b - 1575; }
    else               { li = 5; rel = b - 1584; }

    const int C  = d_C[li];
    const int H  = d_H[li];
    const int W  = H;
    const int an = d_AN[li];
    const int aoff = d_AOFF[li];
    const int nx = d_NX[li];
    const int Mc = an * 81;
    const int M  = an * 85;
    const int HW = H * W;
    const int Ncols = NIMG * HW;
    const int K  = C * 9;            // multiple of 16 for all levels

    const float* __restrict__ feat = P.feat[li];
    const float* __restrict__ cw   = P.cw[li];
    const float* __restrict__ cb   = P.cb[li];
    const float* __restrict__ rw   = P.rw[li];
    const float* __restrict__ rb   = P.rb[li];

    __shared__ __align__(16) float2 As2[2][16][128];   // duplicated A (M=128)
    __shared__ __align__(16) float  Bs[2][16][64];     // B (N=64)

    const int tid = threadIdx.x;
    const int m0  = (rel / nx) * 128;
    const int n0  = (rel % nx) * 64;

    // ---- loader mapping ----
    // A: thread t loads row (m0 + t), 16 k-values (4 x float4)
    // B: 64 lanes (lmB) x 2 k-halves (lk8 = 0 or 8)
    const int lmB = tid & 63;
    const int lk8 = (tid >> 6) * 8;

    const int am = m0 + tid;
    const float* arow = nullptr;
    if (am < Mc)      arow = cw + (size_t)am * K;
    else if (am < M)  arow = rw + (size_t)(am - Mc) * K;

    const int col = n0 + lmB;
    const bool colv = (col < Ncols);
    int img = 0, oh = 0, ow = 0;
    if (colv) { img = col / HW; int r = col % HW; oh = r / W; ow = r % W; }
    const float* fimg = feat + (size_t)img * C * HW;

    const int ty = tid >> 3;   // 0..15 (M dir)
    const int tx = tid & 7;    // 0..7  (N dir)

    // cascaded packed accumulators: mid (FFMA2 target) + hi (flush target)
    unsigned long long accm[8][4], acch[8][4];
#pragma unroll
    for (int i = 0; i < 8; ++i)
#pragma unroll
        for (int u = 0; u < 4; ++u) { accm[i][u] = 0ull; acch[i][u] = 0ull; }

    const int nch = K >> 4;

    // ---- prefetch chunk 0 into registers ----
    float pa[16], pb[8];
    {
#pragma unroll
        for (int u = 0; u < 16; ++u) pa[u] = 0.f;
        if (arow) {
#pragma unroll
            for (int q = 0; q < 4; ++q) {
                const float4 v = *(const float4*)(arow + q * 4);
                pa[q * 4 + 0] = v.x; pa[q * 4 + 1] = v.y;
                pa[q * 4 + 2] = v.z; pa[q * 4 + 3] = v.w;
            }
        }
#pragma unroll
        for (int u = 0; u < 8; ++u) {
            const int k = lk8 + u;
            float v = 0.f;
            if (colv) {
                const int c  = k / 9;
                const int r  = k - c * 9;
                const int ih = oh + r / 3 - 1;
                const int iw = ow + (r % 3) - 1;
                if ((unsigned)ih < (unsigned)H && (unsigned)iw < (unsigned)W)
                    v = fimg[((size_t)c * H + ih) * W + iw];
            }
            pb[u] = v;
        }
    }

    int fcnt = 0;
    int cur  = 0;
    for (int ch = 0; ch < nch; ++ch) {
        // ---- commit prefetched chunk to smem[cur] ----
#pragma unroll
        for (int u = 0; u < 16; ++u)
            As2[cur][u][tid] = make_float2(pa[u], pa[u]);
#pragma unroll
        for (int u = 0; u < 8; ++u)
            Bs[cur][lk8 + u][lmB] = pb[u];
        __syncthreads();

        // ---- issue prefetch of next chunk (overlaps with compute) ----
        if (ch + 1 < nch) {
            const int k0 = (ch + 1) << 4;
            if (arow) {
#pragma unroll
                for (int q = 0; q < 4; ++q) {
                    const float4 v = *(const float4*)(arow + k0 + q * 4);
                    pa[q * 4 + 0] = v.x; pa[q * 4 + 1] = v.y;
                    pa[q * 4 + 2] = v.z; pa[q * 4 + 3] = v.w;
                }
            }
#pragma unroll
            for (int u = 0; u < 8; ++u) {
                const int k = k0 + lk8 + u;
                float v = 0.f;
                if (colv) {
                    const int c  = k / 9;
                    const int r  = k - c * 9;
                    const int ih = oh + r / 3 - 1;
                    const int iw = ow + (r % 3) - 1;
                    if ((unsigned)ih < (unsigned)H && (unsigned)iw < (unsigned)W)
                        v = fimg[((size_t)c * H + ih) * W + iw];
                }
                pb[u] = v;
            }
        }

        // ---- compute 16-deep chunk from smem[cur] ----
#pragma unroll
        for (int kk = 0; kk < 16; ++kk) {
            const ulonglong2 a01 = *(const ulonglong2*)&As2[cur][kk][ty * 8];
            const ulonglong2 a23 = *(const ulonglong2*)&As2[cur][kk][ty * 8 + 2];
            const ulonglong2 a45 = *(const ulonglong2*)&As2[cur][kk][ty * 8 + 4];
            const ulonglong2 a67 = *(const ulonglong2*)&As2[cur][kk][ty * 8 + 6];
            const ulonglong2 b0  = *(const ulonglong2*)&Bs[cur][kk][tx * 8];
            const ulonglong2 b1  = *(const ulonglong2*)&Bs[cur][kk][tx * 8 + 4];
            const unsigned long long ap[8] =
                { a01.x, a01.y, a23.x, a23.y, a45.x, a45.y, a67.x, a67.y };
            const unsigned long long bp[4] = { b0.x, b0.y, b1.x, b1.y };
#pragma unroll
            for (int i = 0; i < 8; ++i)
#pragma unroll
                for (int u = 0; u < 4; ++u)
                    asm("fma.rn.f32x2 %0, %1, %2, %0;"
                        : "+l"(accm[i][u]) : "l"(ap[i]), "l"(bp[u]));
        }

        // ---- cascade flush every 12 chunks (192 k-values, as before) ----
        if (++fcnt == 12) {
            fcnt = 0;
#pragma unroll
            for (int i = 0; i < 8; ++i)
#pragma unroll
                for (int u = 0; u < 4; ++u) {
                    asm("add.rn.f32x2 %0, %0, %1;"
                        : "+l"(acch[i][u]) : "l"(accm[i][u]));
                    accm[i][u] = 0ull;
                }
        }
        cur ^= 1;
    }

    // ---- epilogue: bias add + scatter to g_cls / g_reg ----
#pragma unroll
    for (int i = 0; i < 8; ++i) {
        const int m = m0 + ty * 8 + i;
        if (m >= M) continue;
        const float bias = (m < Mc) ? cb[m] : rb[m - Mc];
#pragma unroll
        for (int u = 0; u < 4; ++u) {
            const float lo = __uint_as_float((unsigned)(acch[i][u] & 0xFFFFFFFFull));
            const float hi = __uint_as_float((unsigned)(acch[i][u] >> 32));
#pragma unroll
            for (int half = 0; half < 2; ++half) {
                const int j  = 2 * u + half;
                const int cc = n0 + tx * 8 + j;
                if (cc >= Ncols) continue;
                const float v = (half ? hi : lo) + bias;
                const int im = cc / HW;
                const int r  = cc % HW;
                const int o_h = r / W, o_w = r - o_h * W;
                const int base = (o_h * W + o_w) * an;
                if (m < Mc) {
                    const int a = m / 81, t = m - a * 81;
                    const int anc = aoff + base + a;
                    g_cls[((size_t)im * NANCH + anc) * 81 + t] = v;
                } else {
                    const int mm = m - Mc;
                    const int a = mm >> 2, t = mm & 3;
                    const int anc = aoff + base + a;
                    g_reg[((size_t)im * NANCH + anc) * 4 + t] = v;
                }
            }
        }
    }
}

// ---------------- softmax over 81 classes, drop background, threshold ----
// fused histogram; sum in fp64 (rounded once).
__global__ void softmax_kernel()
{
    const int w    = (blockIdx.x * blockDim.x + threadIdx.x) >> 5;
    const int lane = threadIdx.x & 31;
    if (w >= NIMG * NANCH) return;
    const int img  = w / NANCH;
    const float* in = g_cls + (size_t)w * 81;
    unsigned int* h = g_hist + img * 65536;

    const float NEG = -3.0e38f;
    float v0 = in[lane];
    float v1 = (lane + 32 < 81) ? in[lane + 32] : NEG;
    float v2 = (lane + 64 < 81) ? in[lane + 64] : NEG;
    float m = fmaxf(v0, fmaxf(v1, v2));
#pragma unroll
    for (int off = 16; off > 0; off >>= 1)
        m = fmaxf(m, __shfl_xor_sync(0xFFFFFFFFu, m, off));
    float e0 = expf(v0 - m);
    float e1 = (lane + 32 < 81) ? expf(v1 - m) : 0.f;
    float e2 = (lane + 64 < 81) ? expf(v2 - m) : 0.f;
    double s = (double)e0 + (double)e1 + (double)e2;
#pragma unroll
    for (int off = 16; off > 0; off >>= 1)
        s += __shfl_xor_sync(0xFFFFFFFFu, s, off);
    const float sf = (float)s;

    float* out = g_scr + (size_t)w * NCLS;
    if (lane >= 1) {
        float p = e0 / sf;
        const bool pos = (p > 0.01f);
        out[lane - 1] = pos ? p : 0.f;
        if (pos) atomicAdd(&h[__float_as_uint(p) >> 16], 1u);
    }
    if (lane + 32 < 81) {
        float p = e1 / sf;
        const bool pos = (p > 0.01f);
        out[lane + 31] = pos ? p : 0.f;
        if (pos) atomicAdd(&h[__float_as_uint(p) >> 16], 1u);
    }
    if (lane + 64 < 81) {
        float p = e2 / sf;
        const bool pos = (p > 0.01f);
        out[lane + 63] = pos ? p : 0.f;
        if (pos) atomicAdd(&h[__float_as_uint(p) >> 16], 1u);
    }
}

// ---------------- find boundary bucket (suffix count >= 400) ----------------
__global__ void boundary_kernel()
{
    __shared__ unsigned int cs[256];
    const int img = blockIdx.x, t = threadIdx.x;
    const unsigned int* h = g_hist + img * 65536;
    unsigned int s = 0;
    const int base = t * 256;
    for (int b = 0; b < 256; ++b) s += h[base + b];
    cs[t] = s;
    __syncthreads();
    if (t == 0) {
        unsigned int acc = 0, thr = 0;
        int chunk = -1;
        for (int c = 255; c >= 0; --c) {
            if (acc + cs[c] >= NCAND) { chunk = c; break; }
            acc += cs[c];
        }
        if (chunk >= 0) {
            for (int b = chunk * 256 + 255; b >= chunk * 256; --b) {
                acc += h[b];
                if (acc >= NCAND) { thr = (unsigned)b; break; }
            }
        }
        g_thr[img] = thr;
        g_cnt[img] = 0;
    }
}

// ---------------- collect top-400 superset ----------------
__global__ void collect_kernel()
{
    const int img = blockIdx.y;
    const unsigned int thr = g_thr[img];
    const float* f = g_scr + (size_t)img * FLATC;
    for (int j = blockIdx.x * blockDim.x + threadIdx.x; j < FLATC;
         j += gridDim.x * blockDim.x) {
        const float v = f[j];
        if (v > 0.f && (__float_as_uint(v) >> 16) >= thr) {
            const int p = atomicAdd(&g_cnt[img], 1);
            if (p < CAP) {
                g_cand_v[img * CAP + p] = v;
                g_cand_i[img * CAP + p] = j;
            }
        }
    }
}

// ---------------- bitonic sort (desc by value, asc by index on ties) ------
__global__ void __launch_bounds__(512) sort_kernel()
{
    __shared__ unsigned long long keys[CAP];
    const int img = blockIdx.x, tid = threadIdx.x;
    int n = g_cnt[img];
    if (n > CAP) n = CAP;

    for (int i = tid; i < CAP; i += 512) {
        unsigned long long key = 0ull;
        if (i < n) {
            const unsigned vb = __float_as_uint(g_cand_v[img * CAP + i]);
            const unsigned ix = (unsigned)g_cand_i[img * CAP + i];
            key = ((unsigned long long)vb << 32) | (0xFFFFFFFFu - ix);
        }
        keys[i] = key;
    }
    __syncthreads();

    for (int k = 2; k <= CAP; k <<= 1) {
        for (int j = k >> 1; j > 0; j >>= 1) {
            for (int i = tid; i < CAP; i += 512) {
                const int ixj = i ^ j;
                if (ixj > i) {
                    const bool desc = ((i & k) == 0);
                    const unsigned long long a = keys[i], b = keys[ixj];
                    if (desc ? (a < b) : (a > b)) { keys[i] = b; keys[ixj] = a; }
                }
            }
            __syncthreads();
        }
    }

    if (tid < NCAND) {
        const unsigned long long key = keys[tid];
        g_top_v[img * NCAND + tid] = __uint_as_float((unsigned)(key >> 32));
        g_top_i[img * NCAND + tid] = (int)(0xFFFFFFFFu - (unsigned)(key & 0xFFFFFFFFull));
    }
    __syncthreads();
    // padding path: fewer than 400 positives -> lax.top_k fills with the
    // lowest-index zero entries
    if (tid == 0 && n < NCAND) {
        const float* f = g_scr + (size_t)img * FLATC;
        int p = n;
        for (int j = 0; j < FLATC && p < NCAND; ++j) {
            if (f[j] == 0.0f) {
                g_top_v[img * NCAND + p] = 0.f;
                g_top_i[img * NCAND + p] = j;
                ++p;
            }
        }
    }
}

// ---------------- decode + class-aware NMS + final top-200 ----------------
__global__ void __launch_bounds__(512)
postnms_kernel(const float* __restrict__ priors, float* __restrict__ out)
{
    __shared__ float sx1[NCAND], sy1[NCAND], sx2[NCAND], sy2[NCAND];
    __shared__ float ox1[NCAND], oy1[NCAND], ox2[NCAND], oy2[NCAND], oar[NCAND];
    __shared__ float s_sc[NCAND];
    __shared__ int   s_cls[NCAND], s_keep[NCAND];
    __shared__ int   s_fi[NOUT];

    const int img = blockIdx.x, tid = threadIdx.x;

    if (tid < NCAND) {
        const float v  = g_top_v[img * NCAND + tid];
        const int idx  = g_top_i[img * NCAND + tid];
        const int cls  = idx % NCLS + 1;
        const int anc  = idx / NCLS;
        const float* d = g_reg + ((size_t)img * NANCH + anc) * 4;
        const float* p = priors + (size_t)anc * 4;
        const float cx = p[0] + d[0] * 0.1f * p[2];
        const float cy = p[1] + d[1] * 0.1f * p[3];
        const float w  = p[2] * expf(fminf(d[2] * 0.2f, CLIPV));
        const float h  = p[3] * expf(fminf(d[3] * 0.2f, CLIPV));
        float x1 = cx - 0.5f * w, y1 = cy - 0.5f * h;
        float x2 = cx + 0.5f * w, y2 = cy + 0.5f * h;
        x1 = fminf(fmaxf(x1, 0.f), 300.f);
        y1 = fminf(fmaxf(y1, 0.f), 300.f);
        x2 = fminf(fmaxf(x2, 0.f), 300.f);
        y2 = fminf(fmaxf(y2, 0.f), 300.f);
        const bool valid = (v > 0.f) && (x2 > x1) && (y2 > y1);
        sx1[tid] = x1; sy1[tid] = y1; sx2[tid] = x2; sy2[tid] = y2;
        s_sc[tid] = valid ? v : 0.f;
        s_cls[tid] = cls;
        s_keep[tid] = valid ? 1 : 0;
        // class offset applied BEFORE area/IoU, exactly as in the reference
        const float off = (float)cls * 301.0f;
        const float a1 = x1 + off, b1 = y1 + off, a2 = x2 + off, b2 = y2 + off;
        ox1[tid] = a1; oy1[tid] = b1; ox2[tid] = a2; oy2[tid] = b2;
        oar[tid] = (a2 - a1) * (b2 - b1);
    }
    __syncthreads();

    // greedy NMS, iteration order identical to the fori_loop
    for (int i = 0; i < NCAND; ++i) {
        if (s_keep[i]) {
            const int j = tid;
            if (j > i && j < NCAND && s_keep[j]) {
                const float ltx = fmaxf(ox1[i], ox1[j]);
                const float lty = fmaxf(oy1[i], oy1[j]);
                const float rbx = fminf(ox2[i], ox2[j]);
                const float rby = fminf(oy2[i], oy2[j]);
                const float ww = fmaxf(rbx - ltx, 0.f);
                const float hh = fmaxf(rby - lty, 0.f);
                const float inter = ww * hh;
                const float iou = inter / (oar[i] + oar[j] - inter + 1e-9f);
                if (iou > 0.45f) s_keep[j] = 0;
            }
        }
        __syncthreads();
    }

    // final top_k(where(keep, s, 0), 200):
    // kept positions ascending (s is already sorted desc), then zero-valued
    // (non-kept) positions ascending -- matches value-desc/index-asc ties.
    if (tid == 0) {
        int p = 0;
        for (int i = 0; i < NCAND && p < NOUT; ++i) if (s_keep[i])  s_fi[p++] = i;
        for (int i = 0; i < NCAND && p < NOUT; ++i) if (!s_keep[i]) s_fi[p++] = i;
    }
    __syncthreads();

    if (tid < NOUT) {
        const int o = s_fi[tid];
        const float fsv = s_keep[o] ? s_sc[o] : 0.f;
        const size_t bo = ((size_t)img * NOUT + tid) * 4;
        out[bo + 0] = sx1[o];
        out[bo + 1] = sy1[o];
        out[bo + 2] = sx2[o];
        out[bo + 3] = sy2[o];
        out[(size_t)NIMG * NOUT * 4 + img * NOUT + tid] = fsv;
        out[(size_t)NIMG * NOUT * 5 + img * NOUT + tid] =
            (fsv > 0.f) ? (float)s_cls[o] : 0.f;
    }
}

// ---------------- host launch ----------------
extern "C" void kernel_launch(void* const* d_in, const int* in_sizes, int n_in,
                              void* d_out, int out_size)
{
    (void)out_size;
    // input-order detection: signature order has feat1 (5,914,624 elems) at
    // slot 1; dict-insertion order has cls_w0 (1,492,992) there.
    const bool sig = (n_in > 1 && in_sizes[1] == 16 * 1024 * 19 * 19);
    int fI[6], cwI[6], cbI[6], rwI[6], rbI[6];
    for (int i = 0; i < 6; ++i) {
        if (sig) {
            fI[i] = i;
            cwI[i] = 6 + 2 * i;  cbI[i] = 7 + 2 * i;
            rwI[i] = 18 + 2 * i; rbI[i] = 19 + 2 * i;
        } else {
            fI[i] = 5 * i;
            cwI[i] = 5 * i + 1; cbI[i] = 5 * i + 2;
            rwI[i] = 5 * i + 3; rbI[i] = 5 * i + 4;
        }
    }
    const float* priors = (const float*)d_in[30];
    float* out = (float*)d_out;

    HeadPtrs P;
    for (int i = 0; i < 6; ++i) {
        P.feat[i] = (const float*)d_in[fI[i]];
        P.cw[i]   = (const float*)d_in[cwI[i]];
        P.cb[i]   = (const float*)d_in[cbI[i]];
        P.rw[i]   = (const float*)d_in[rwI[i]];
        P.rb[i]   = (const float*)d_in[rbI[i]];
    }

    zero_kernel<<<512, 256>>>();

    // single merged launch: 364(L1) + 1083(L0) + 100(L2) + 28(L3) + 9(L4) + 3(L5)
    head_gemm_all<<<GRID_TOTAL, 128>>>(P);

    softmax_kernel<<<(NIMG * NANCH + 7) / 8, 256>>>();   // hist fused in
    boundary_kernel<<<NIMG, 256>>>();
    collect_kernel<<<dim3(256, NIMG), 256>>>();
    sort_kernel<<<NIMG, 512>>>();
    postnms_kernel<<<NIMG, 512>>>(priors, out);
}

// round 15
// speedup vs baseline: 1.3005x; 1.1999x over previous
#include <cuda_runtime.h>
#include <cuda_bf16.h>
#include <math.h>
#include <stdint.h>

#define NIMG   16
#define NANCH  8732
#define NCLS   80
#define FLATC  (NANCH * NCLS)     // 698560
#define NCAND  400
#define NOUT   200
#define CAP    4096
#define CLIPV  4.135166556742356f // log(1000/16)

// ---------------- device scratch (no allocations allowed) ----------------
__device__ float        g_cls[(size_t)NIMG * NANCH * 81];   // logits
__device__ float        g_scr[(size_t)NIMG * FLATC];        // thresholded softmax scores
__device__ float        g_reg[(size_t)NIMG * NANCH * 4];    // box deltas
__device__ unsigned int g_hist[NIMG * 65536];
__device__ int          g_cnt[NIMG];
__device__ unsigned int g_thr[NIMG];
__device__ float        g_cand_v[NIMG * CAP];
__device__ int          g_cand_i[NIMG * CAP];
__device__ float        g_top_v[NIMG * NCAND];
__device__ int          g_top_i[NIMG * NCAND];

// ---------------- zero histograms ----------------
__global__ void zero_kernel()
{
    int i  = blockIdx.x * blockDim.x + threadIdx.x;
    int st = gridDim.x * blockDim.x;
    for (int t = i; t < NIMG * 65536; t += st) g_hist[t] = 0u;
}

// ============ conv heads via warp-level HMMA (bf16 3-way split) ============
// mma.sync.m16n8k16 bf16 (PTX sm_80+, works on plain sm_103 targets, unlike
// tcgen05). a = a0+a1+a2 bf16 split; 6 product terms (a0b0,a0b1,a1b0,a1b1,
// a0b2,a2b0) -> split error ~1.2e-7. fp32 HMMA accumulation + register
// cascade (acc->hi every 12 k32-chunks = 384 k) keeps sequential-chain noise
// at the level that already passes (rel_err ~2.5e-7 regime).
struct HeadPtrs {
    const float* feat[6];
    const float* cw[6];
    const float* cb[6];
    const float* rw[6];
    const float* rb[6];
};

__device__ __constant__ int d_C[6]    = {512, 1024, 512, 256, 256, 256};
__device__ __constant__ int d_H[6]    = {38, 19, 10, 5, 3, 1};
__device__ __constant__ int d_AN[6]   = {4, 6, 6, 6, 4, 4};
__device__ __constant__ int d_AOFF[6] = {0, 5776, 7942, 8542, 8692, 8728};
__device__ __constant__ int d_NX[6]   = {181, 46, 13, 4, 2, 1};  // ceil(Nc/128)

#define PITCH   80                   // 64B data + 16B pad: conflict-free ldmatrix
#define CTILE   (128 * PITCH)        // one component tile: 10240 B
#define SMEM_HM (6 * CTILE)          // 61440 B (3 A comps + 3 B comps)

__device__ __forceinline__ uint32_t bfpack(float x, float y)
{
    const __nv_bfloat16 hx = __float2bfloat16(x);
    const __nv_bfloat16 hy = __float2bfloat16(y);
    return (uint32_t)__bfloat16_as_ushort(hx) |
           ((uint32_t)__bfloat16_as_ushort(hy) << 16);
}

// split 8 consecutive values into 3 bf16 components; store 16B per comp tile
__device__ __forceinline__ void split_store8(char* base, uint32_t off, const float* v)
{
    uint32_t p0[4], p1[4], p2[4];
#pragma unroll
    for (int u = 0; u < 4; ++u) {
        const float x = v[2 * u], y = v[2 * u + 1];
        const __nv_bfloat16 hx = __float2bfloat16(x);
        const __nv_bfloat16 hy = __float2bfloat16(y);
        const float rx = x - __bfloat162float(hx);
        const float ry = y - __bfloat162float(hy);
        p0[u] = (uint32_t)__bfloat16_as_ushort(hx) |
                ((uint32_t)__bfloat16_as_ushort(hy) << 16);
        const __nv_bfloat16 gx = __float2bfloat16(rx);
        const __nv_bfloat16 gy = __float2bfloat16(ry);
        const float sx = rx - __bfloat162float(gx);
        const float sy = ry - __bfloat162float(gy);
        p1[u] = (uint32_t)__bfloat16_as_ushort(gx) |
                ((uint32_t)__bfloat16_as_ushort(gy) << 16);
        p2[u] = bfpack(sx, sy);
    }
    *(uint4*)(base + off)              = make_uint4(p0[0], p0[1], p0[2], p0[3]);
    *(uint4*)(base + CTILE + off)      = make_uint4(p1[0], p1[1], p1[2], p1[3]);
    *(uint4*)(base + 2 * CTILE + off)  = make_uint4(p2[0], p2[1], p2[2], p2[3]);
}

__device__ __forceinline__ void zero_store8(char* base, uint32_t off)
{
    const uint4 z = make_uint4(0, 0, 0, 0);
    *(uint4*)(base + off)             = z;
    *(uint4*)(base + CTILE + off)     = z;
    *(uint4*)(base + 2 * CTILE + off) = z;
}

__device__ __forceinline__ void ldsm4(uint32_t* r, uint32_t addr)
{
    asm volatile("ldmatrix.sync.aligned.m8n8.x4.shared.b16 {%0,%1,%2,%3}, [%4];"
                 : "=r"(r[0]), "=r"(r[1]), "=r"(r[2]), "=r"(r[3]) : "r"(addr));
}

__device__ __forceinline__ void mma16816(float* c, const uint32_t* a, const uint32_t* b)
{
    asm volatile(
        "mma.sync.aligned.m16n8k16.row.col.f32.bf16.bf16.f32 "
        "{%0,%1,%2,%3},{%4,%5,%6,%7},{%8,%9},{%0,%1,%2,%3};"
        : "+f"(c[0]), "+f"(c[1]), "+f"(c[2]), "+f"(c[3])
        : "r"(a[0]), "r"(a[1]), "r"(a[2]), "r"(a[3]), "r"(b[0]), "r"(b[1]));
}

__global__ void __launch_bounds__(256, 1)
head_gemm_hmma(const HeadPtrs P)
{
    // ---- block -> (level, tile) mapping; work-heavy levels first ----
    const int b = blockIdx.x;
    int li, rel;
    if      (b < 184) { li = 1; rel = b; }
    else if (b < 727) { li = 0; rel = b - 184; }
    else if (b < 779) { li = 2; rel = b - 727; }
    else if (b < 795) { li = 3; rel = b - 779; }
    else if (b < 801) { li = 4; rel = b - 795; }
    else              { li = 5; rel = b - 801; }

    const int C  = d_C[li];
    const int H  = d_H[li];
    const int W  = H;
    const int an = d_AN[li];
    const int aoff = d_AOFF[li];
    const int nx = d_NX[li];
    const int Mc = an * 81;
    const int M  = an * 85;
    const int HW = H * W;
    const int Ncols = NIMG * HW;
    const int K  = C * 9;            // 4608 / 9216 / 2304: all % 384 == 0

    const float* __restrict__ feat = P.feat[li];
    const float* __restrict__ cw   = P.cw[li];
    const float* __restrict__ cb   = P.cb[li];
    const float* __restrict__ rw   = P.rw[li];
    const float* __restrict__ rb   = P.rb[li];

    extern __shared__ __align__(16) char dsm[];
    uint32_t sb;
    asm("{ .reg .u64 t; cvta.to.shared.u64 t, %1; cvt.u32.u64 %0, t; }"
        : "=r"(sb) : "l"(dsm));

    const int tid  = threadIdx.x;
    const int wid  = tid >> 5, lane = tid & 31;
    const int m0   = (rel / nx) * 128;
    const int n0   = (rel % nx) * 128;

    // ---- converter role: threads 0-127 -> A rows, 128-255 -> B cols ----
    const bool isA = (tid < 128);
    const int crow = isA ? tid : tid - 128;

    const float* arow = nullptr;
    if (isA) {
        const int am = m0 + crow;
        if (am < Mc)      arow = cw + (size_t)am * K;
        else if (am < M)  arow = rw + (size_t)(am - Mc) * K;
    }
    bool colv = false;
    int img = 0, oh = 0, ow = 0;
    if (!isA) {
        const int col = n0 + crow;
        colv = (col < Ncols);
        if (colv) { img = col / HW; int r = col % HW; oh = r / W; ow = r % W; }
    }
    const float* fimg = feat + (size_t)img * C * HW;
    const uint32_t cvt_off = (uint32_t)crow * PITCH;

    // ---- warp tile mapping: 8 warps = 2 m-halves x 4 n-quarters ----
    const int m0w = (wid >> 2) * 64;   // 0 or 64
    const int n0w = (wid & 3) * 32;    // 0,32,64,96

    // per-lane ldmatrix offsets (within a component tile)
    const uint32_t a_off = (uint32_t)(m0w + (lane & 15)) * PITCH + (lane >> 4) * 16;
    const uint32_t b_off = (uint32_t)(n0w + (lane & 7) + ((lane >> 4) << 3)) * PITCH
                         + ((lane >> 3) & 1) * 16;

    float acc[4][4][4], hi[4][4][4];
#pragma unroll
    for (int i = 0; i < 4; ++i)
#pragma unroll
        for (int j = 0; j < 4; ++j)
#pragma unroll
            for (int u = 0; u < 4; ++u) { acc[i][j][u] = 0.f; hi[i][j][u] = 0.f; }

    const int nch = K >> 5;          // K-chunks of 32
    int fcnt = 0;

    for (int ch = 0; ch < nch; ++ch) {
        const int k0 = ch << 5;

        // ---- convert/split this chunk into smem component tiles ----
        if (isA) {
            if (arow) {
#pragma unroll
                for (int q = 0; q < 4; ++q) {
                    const float4 v0 = *(const float4*)(arow + k0 + q * 8);
                    const float4 v1 = *(const float4*)(arow + k0 + q * 8 + 4);
                    float va[8] = { v0.x, v0.y, v0.z, v0.w, v1.x, v1.y, v1.z, v1.w };
                    split_store8(dsm, cvt_off + q * 16, va);
                }
            } else if (ch == 0) {
#pragma unroll
                for (int q = 0; q < 4; ++q) zero_store8(dsm, cvt_off + q * 16);
            }
        } else {
            if (colv) {
#pragma unroll
                for (int q = 0; q < 4; ++q) {
                    float vb[8];
#pragma unroll
                    for (int u = 0; u < 8; ++u) {
                        const int k = k0 + q * 8 + u;
                        float v = 0.f;
                        const int c  = k / 9;
                        const int r  = k - c * 9;
                        const int ih = oh + r / 3 - 1;
                        const int iw = ow + (r % 3) - 1;
                        if ((unsigned)ih < (unsigned)H && (unsigned)iw < (unsigned)W)
                            v = fimg[((size_t)c * H + ih) * W + iw];
                        vb[u] = v;
                    }
                    split_store8(dsm + 3 * CTILE, cvt_off + q * 16, vb);
                }
            } else if (ch == 0) {
#pragma unroll
                for (int q = 0; q < 4; ++q) zero_store8(dsm + 3 * CTILE, cvt_off + q * 16);
            }
        }
        __syncthreads();

        // ---- MMA phase: 6 split-product pairs, grouped by A component ----
#pragma unroll
        for (int g = 0; g < 3; ++g) {
            const uint32_t tAg = sb + g * CTILE;
            const int nbj = (g == 0) ? 3 : ((g == 1) ? 2 : 1);
#pragma unroll
            for (int sk = 0; sk < 2; ++sk) {
                uint32_t av[4][4];
#pragma unroll
                for (int mf = 0; mf < 4; ++mf)
                    ldsm4(av[mf], tAg + a_off + mf * 16 * PITCH + sk * 32);
#pragma unroll
                for (int bj = 0; bj < 3; ++bj) {
                    if (bj >= nbj) break;
                    const uint32_t tBg = sb + (3 + bj) * CTILE;
                    uint32_t bv[2][4];
                    ldsm4(bv[0], tBg + b_off + sk * 32);
                    ldsm4(bv[1], tBg + b_off + 16 * PITCH + sk * 32);
#pragma unroll
                    for (int mf = 0; mf < 4; ++mf)
#pragma unroll
                        for (int nf = 0; nf < 4; ++nf)
                            mma16816(acc[mf][nf], av[mf], &bv[nf >> 1][(nf & 1) * 2]);
                }
            }
        }
        __syncthreads();

        // ---- cascade flush every 12 chunks (384 k-values) ----
        if (++fcnt == 12) {
            fcnt = 0;
#pragma unroll
            for (int i = 0; i < 4; ++i)
#pragma unroll
                for (int j = 0; j < 4; ++j)
#pragma unroll
                    for (int u = 0; u < 4; ++u) {
                        hi[i][j][u] += acc[i][j][u];
                        acc[i][j][u] = 0.f;
                    }
        }
    }

    // ---- epilogue: bias add + scatter (from hi; acc drained: nch % 12 == 0)
#pragma unroll
    for (int mf = 0; mf < 4; ++mf) {
        const int rb_ = m0 + m0w + mf * 16 + (lane >> 2);
#pragma unroll
        for (int half = 0; half < 2; ++half) {
            const int m = rb_ + half * 8;
            if (m >= M) continue;
            const float bias = (m < Mc) ? cb[m] : rb[m - Mc];
#pragma unroll
            for (int nf = 0; nf < 4; ++nf) {
#pragma unroll
                for (int e = 0; e < 2; ++e) {
                    const int cc = n0 + n0w + nf * 8 + (lane & 3) * 2 + e;
                    if (cc >= Ncols) continue;
                    const float v = hi[mf][nf][half * 2 + e] + bias;
                    const int im = cc / HW;
                    const int r  = cc % HW;
                    const int o_h = r / W, o_w = r - o_h * W;
                    const int base = (o_h * W + o_w) * an;
                    if (m < Mc) {
                        const int a = m / 81, t = m - a * 81;
                        const int anc = aoff + base + a;
                        g_cls[((size_t)im * NANCH + anc) * 81 + t] = v;
                    } else {
                        const int mm = m - Mc;
                        const int a = mm >> 2, t = mm & 3;
                        const int anc = aoff + base + a;
                        g_reg[((size_t)im * NANCH + anc) * 4 + t] = v;
                    }
                }
            }
        }
    }
}

// ---------------- softmax over 81 classes, drop background, threshold ----
// fused histogram; sum in fp64 (rounded once).
__global__ void softmax_kernel()
{
    const int w    = (blockIdx.x * blockDim.x + threadIdx.x) >> 5;
    const int lane = threadIdx.x & 31;
    if (w >= NIMG * NANCH) return;
    const int img  = w / NANCH;
    const float* in = g_cls + (size_t)w * 81;
    unsigned int* h = g_hist + img * 65536;

    const float NEG = -3.0e38f;
    float v0 = in[lane];
    float v1 = (lane + 32 < 81) ? in[lane + 32] : NEG;
    float v2 = (lane + 64 < 81) ? in[lane + 64] : NEG;
    float m = fmaxf(v0, fmaxf(v1, v2));
#pragma unroll
    for (int off = 16; off > 0; off >>= 1)
        m = fmaxf(m, __shfl_xor_sync(0xFFFFFFFFu, m, off));
    float e0 = expf(v0 - m);
    float e1 = (lane + 32 < 81) ? expf(v1 - m) : 0.f;
    float e2 = (lane + 64 < 81) ? expf(v2 - m) : 0.f;
    double s = (double)e0 + (double)e1 + (double)e2;
#pragma unroll
    for (int off = 16; off > 0; off >>= 1)
        s += __shfl_xor_sync(0xFFFFFFFFu, s, off);
    const float sf = (float)s;

    float* out = g_scr + (size_t)w * NCLS;
    if (lane >= 1) {
        float p = e0 / sf;
        const bool pos = (p > 0.01f);
        out[lane - 1] = pos ? p : 0.f;
        if (pos) atomicAdd(&h[__float_as_uint(p) >> 16], 1u);
    }
    if (lane + 32 < 81) {
        float p = e1 / sf;
        const bool pos = (p > 0.01f);
        out[lane + 31] = pos ? p : 0.f;
        if (pos) atomicAdd(&h[__float_as_uint(p) >> 16], 1u);
    }
    if (lane + 64 < 81) {
        float p = e2 / sf;
        const bool pos = (p > 0.01f);
        out[lane + 63] = pos ? p : 0.f;
        if (pos) atomicAdd(&h[__float_as_uint(p) >> 16], 1u);
    }
}

// ---------------- find boundary bucket (suffix count >= 400) ----------------
__global__ void boundary_kernel()
{
    __shared__ unsigned int cs[256];
    const int img = blockIdx.x, t = threadIdx.x;
    const unsigned int* h = g_hist + img * 65536;
    unsigned int s = 0;
    const int base = t * 256;
    for (int b = 0; b < 256; ++b) s += h[base + b];
    cs[t] = s;
    __syncthreads();
    if (t == 0) {
        unsigned int acc = 0, thr = 0;
        int chunk = -1;
        for (int c = 255; c >= 0; --c) {
            if (acc + cs[c] >= NCAND) { chunk = c; break; }
            acc += cs[c];
        }
        if (chunk >= 0) {
            for (int b = chunk * 256 + 255; b >= chunk * 256; --b) {
                acc += h[b];
                if (acc >= NCAND) { thr = (unsigned)b; break; }
            }
        }
        g_thr[img] = thr;
        g_cnt[img] = 0;
    }
}

// ---------------- collect top-400 superset ----------------
__global__ void collect_kernel()
{
    const int img = blockIdx.y;
    const unsigned int thr = g_thr[img];
    const float* f = g_scr + (size_t)img * FLATC;
    for (int j = blockIdx.x * blockDim.x + threadIdx.x; j < FLATC;
         j += gridDim.x * blockDim.x) {
        const float v = f[j];
        if (v > 0.f && (__float_as_uint(v) >> 16) >= thr) {
            const int p = atomicAdd(&g_cnt[img], 1);
            if (p < CAP) {
                g_cand_v[img * CAP + p] = v;
                g_cand_i[img * CAP + p] = j;
            }
        }
    }
}

// ---------------- bitonic sort (desc by value, asc by index on ties) ------
__global__ void __launch_bounds__(512) sort_kernel()
{
    __shared__ unsigned long long keys[CAP];
    const int img = blockIdx.x, tid = threadIdx.x;
    int n = g_cnt[img];
    if (n > CAP) n = CAP;

    for (int i = tid; i < CAP; i += 512) {
        unsigned long long key = 0ull;
        if (i < n) {
            const unsigned vb = __float_as_uint(g_cand_v[img * CAP + i]);
            const unsigned ix = (unsigned)g_cand_i[img * CAP + i];
            key = ((unsigned long long)vb << 32) | (0xFFFFFFFFu - ix);
        }
        keys[i] = key;
    }
    __syncthreads();

    for (int k = 2; k <= CAP; k <<= 1) {
        for (int j = k >> 1; j > 0; j >>= 1) {
            for (int i = tid; i < CAP; i += 512) {
                const int ixj = i ^ j;
                if (ixj > i) {
                    const bool desc = ((i & k) == 0);
                    const unsigned long long a = keys[i], bb = keys[ixj];
                    if (desc ? (a < bb) : (a > bb)) { keys[i] = bb; keys[ixj] = a; }
                }
            }
            __syncthreads();
        }
    }

    if (tid < NCAND) {
        const unsigned long long key = keys[tid];
        g_top_v[img * NCAND + tid] = __uint_as_float((unsigned)(key >> 32));
        g_top_i[img * NCAND + tid] = (int)(0xFFFFFFFFu - (unsigned)(key & 0xFFFFFFFFull));
    }
    __syncthreads();
    // padding path: fewer than 400 positives -> lax.top_k fills with the
    // lowest-index zero entries
    if (tid == 0 && n < NCAND) {
        const float* f = g_scr + (size_t)img * FLATC;
        int p = n;
        for (int j = 0; j < FLATC && p < NCAND; ++j) {
            if (f[j] == 0.0f) {
                g_top_v[img * NCAND + p] = 0.f;
                g_top_i[img * NCAND + p] = j;
                ++p;
            }
        }
    }
}

// ---------------- decode + class-aware NMS + final top-200 ----------------
__global__ void __launch_bounds__(512)
postnms_kernel(const float* __restrict__ priors, float* __restrict__ out)
{
    __shared__ float sx1[NCAND], sy1[NCAND], sx2[NCAND], sy2[NCAND];
    __shared__ float ox1[NCAND], oy1[NCAND], ox2[NCAND], oy2[NCAND], oar[NCAND];
    __shared__ float s_sc[NCAND];
    __shared__ int   s_cls[NCAND], s_keep[NCAND];
    __shared__ int   s_fi[NOUT];

    const int img = blockIdx.x, tid = threadIdx.x;

    if (tid < NCAND) {
        const float v  = g_top_v[img * NCAND + tid];
        const int idx  = g_top_i[img * NCAND + tid];
        const int cls  = idx % NCLS + 1;
        const int anc  = idx / NCLS;
        const float* d = g_reg + ((size_t)img * NANCH + anc) * 4;
        const float* p = priors + (size_t)anc * 4;
        const float cx = p[0] + d[0] * 0.1f * p[2];
        const float cy = p[1] + d[1] * 0.1f * p[3];
        const float w  = p[2] * expf(fminf(d[2] * 0.2f, CLIPV));
        const float h  = p[3] * expf(fminf(d[3] * 0.2f, CLIPV));
        float x1 = cx - 0.5f * w, y1 = cy - 0.5f * h;
        float x2 = cx + 0.5f * w, y2 = cy + 0.5f * h;
        x1 = fminf(fmaxf(x1, 0.f), 300.f);
        y1 = fminf(fmaxf(y1, 0.f), 300.f);
        x2 = fminf(fmaxf(x2, 0.f), 300.f);
        y2 = fminf(fmaxf(y2, 0.f), 300.f);
        const bool valid = (v > 0.f) && (x2 > x1) && (y2 > y1);
        sx1[tid] = x1; sy1[tid] = y1; sx2[tid] = x2; sy2[tid] = y2;
        s_sc[tid] = valid ? v : 0.f;
        s_cls[tid] = cls;
        s_keep[tid] = valid ? 1 : 0;
        // class offset applied BEFORE area/IoU, exactly as in the reference
        const float off = (float)cls * 301.0f;
        const float a1 = x1 + off, b1 = y1 + off, a2 = x2 + off, b2 = y2 + off;
        ox1[tid] = a1; oy1[tid] = b1; ox2[tid] = a2; oy2[tid] = b2;
        oar[tid] = (a2 - a1) * (b2 - b1);
    }
    __syncthreads();

    // greedy NMS, iteration order identical to the fori_loop
    for (int i = 0; i < NCAND; ++i) {
        if (s_keep[i]) {
            const int j = tid;
            if (j > i && j < NCAND && s_keep[j]) {
                const float ltx = fmaxf(ox1[i], ox1[j]);
                const float lty = fmaxf(oy1[i], oy1[j]);
                const float rbx = fminf(ox2[i], ox2[j]);
                const float rby = fminf(oy2[i], oy2[j]);
                const float ww = fmaxf(rbx - ltx, 0.f);
                const float hh = fmaxf(rby - lty, 0.f);
                const float inter = ww * hh;
                const float iou = inter / (oar[i] + oar[j] - inter + 1e-9f);
                if (iou > 0.45f) s_keep[j] = 0;
            }
        }
        __syncthreads();
    }

    // final top_k(where(keep, s, 0), 200):
    // kept positions ascending (s is already sorted desc), then zero-valued
    // (non-kept) positions ascending -- matches value-desc/index-asc ties.
    if (tid == 0) {
        int p = 0;
        for (int i = 0; i < NCAND && p < NOUT; ++i) if (s_keep[i])  s_fi[p++] = i;
        for (int i = 0; i < NCAND && p < NOUT; ++i) if (!s_keep[i]) s_fi[p++] = i;
    }
    __syncthreads();

    if (tid < NOUT) {
        const int o = s_fi[tid];
        const float fsv = s_keep[o] ? s_sc[o] : 0.f;
        const size_t bo = ((size_t)img * NOUT + tid) * 4;
        out[bo + 0] = sx1[o];
        out[bo + 1] = sy1[o];
        out[bo + 2] = sx2[o];
        out[bo + 3] = sy2[o];
        out[(size_t)NIMG * NOUT * 4 + img * NOUT + tid] = fsv;
        out[(size_t)NIMG * NOUT * 5 + img * NOUT + tid] =
            (fsv > 0.f) ? (float)s_cls[o] : 0.f;
    }
}

// ---------------- host launch ----------------
extern "C" void kernel_launch(void* const* d_in, const int* in_sizes, int n_in,
                              void* d_out, int out_size)
{
    (void)out_size;
    // input-order detection: signature order has feat1 (5,914,624 elems) at
    // slot 1; dict-insertion order has cls_w0 (1,492,992) there.
    const bool sig = (n_in > 1 && in_sizes[1] == 16 * 1024 * 19 * 19);
    int fI[6], cwI[6], cbI[6], rwI[6], rbI[6];
    for (int i = 0; i < 6; ++i) {
        if (sig) {
            fI[i] = i;
            cwI[i] = 6 + 2 * i;  cbI[i] = 7 + 2 * i;
            rwI[i] = 18 + 2 * i; rbI[i] = 19 + 2 * i;
        } else {
            fI[i] = 5 * i;
            cwI[i] = 5 * i + 1; cbI[i] = 5 * i + 2;
            rwI[i] = 5 * i + 3; rbI[i] = 5 * i + 4;
        }
    }
    const float* priors = (const float*)d_in[30];
    float* out = (float*)d_out;

    HeadPtrs P;
    for (int i = 0; i < 6; ++i) {
        P.feat[i] = (const float*)d_in[fI[i]];
        P.cw[i]   = (const float*)d_in[cwI[i]];
        P.cb[i]   = (const float*)d_in[cbI[i]];
        P.rw[i]   = (const float*)d_in[rwI[i]];
        P.rb[i]   = (const float*)d_in[rbI[i]];
    }

    static bool attr_set = false;
    if (!attr_set) {
        cudaFuncSetAttribute(head_gemm_hmma,
                             cudaFuncAttributeMaxDynamicSharedMemorySize,
                             SMEM_HM);
        attr_set = true;
    }

    zero_kernel<<<512, 256>>>();

    // single merged launch: 184(L1) + 543(L0) + 52(L2) + 16(L3) + 6(L4) + 3(L5)
    head_gemm_hmma<<<804, 256, SMEM_HM>>>(P);

    softmax_kernel<<<(NIMG * NANCH + 7) / 8, 256>>>();   // hist fused in
    boundary_kernel<<<NIMG, 256>>>();
    collect_kernel<<<dim3(256, NIMG), 256>>>();
    sort_kernel<<<NIMG, 512>>>();
    postnms_kernel<<<NIMG, 512>>>(priors, out);
}